// round 4
// baseline (speedup 1.0000x reference)
#include <cuda_runtime.h>
#include <cstdint>
#include <float.h>

// Problem dims
#define B_  32
#define D_  256
#define K_  8192
#define HW  1024                  // 32*32
#define N_  32768                 // B_*HW
#define OUT_ELEMS 8388608         // B_*D_*HW
#define LOSS_OFF  OUT_ELEMS
#define IDX_OFF   (OUT_ELEMS + 1)

// GEMM tiling
#define MT 128
#define NT 128
#define KC 32
#define NCHUNKS (K_ / NT)         // 64
#define DCHUNKS (D_ / KC)         // 8
#define STAGES  (NCHUNKS * DCHUNKS)  // 512
#define SMEM_FLOATS (D_*MT + 2*KC*NT + K_)   // 32768 + 8192 + 8192 = 49152 floats = 192KB

// Scratch (no allocations allowed)
__device__ __align__(16) float g_enorm[K_];
__device__ __align__(16) int   g_idx[N_];
__device__ __align__(16) float g_part[1024];

// ---------------------------------------------------------------------------
// Kernel 1: enorm[k] = sum_d e[d,k]^2
// ---------------------------------------------------------------------------
__global__ void enorm_kernel(const float* __restrict__ emb) {
    int k = blockIdx.x * blockDim.x + threadIdx.x;
    float s = 0.f;
#pragma unroll 8
    for (int d = 0; d < D_; ++d) {
        float v = emb[(size_t)d * K_ + k];
        s = fmaf(v, v, s);
    }
    g_enorm[k] = s;
}

// ---------------------------------------------------------------------------
// Kernel 2: fused fp32 GEMM + row argmin.
//   score(n,k) = enorm[k] - 2 * dot(z_n, e_k)   (||z||^2 dropped: row-const)
// A tile [256][128] fully resident in smem; B streamed 32x128 double-buffered
// via cp.async; per-128-col epilogue updates running (min, argmin) in regs.
// ---------------------------------------------------------------------------
__device__ __forceinline__ void cp_async16(void* dst, const void* src) {
    uint32_t s = (uint32_t)__cvta_generic_to_shared(dst);
    asm volatile("cp.async.cg.shared.global [%0], [%1], 16;" :: "r"(s), "l"(src));
}

__global__ __launch_bounds__(256, 1)
void vq_argmin_kernel(const float* __restrict__ lat,
                      const float* __restrict__ emb,
                      float* __restrict__ out_idx_f) {
    extern __shared__ float smem[];
    float* As = smem;                 // [256][128]  (d-major, m contiguous)
    float* Bs = As + D_ * MT;         // [2][32][128]
    float* Es = Bs + 2 * KC * NT;     // [8192]

    const int tid = threadIdx.x;
    const int tx  = tid & 15;         // 16 col-groups of 8
    const int ty  = tid >> 4;         // 16 row-groups of 8
    const int m0  = blockIdx.x * MT;  // 128-row tile, always within one batch b
    const int b   = m0 >> 10;
    const int hw0 = m0 & (HW - 1);

    const float* Abase = lat + (size_t)b * (D_ * HW) + hw0;

    // Load full A tile: As[d][m] = latents[b][d][hw0+m]  (coalesced over m)
    for (int i = tid; i < D_ * (MT / 4); i += 256) {
        int d  = i >> 5;              // 32 float4 per d-row
        int m4 = i & 31;
        float4 v = *reinterpret_cast<const float4*>(Abase + (size_t)d * HW + m4 * 4);
        *reinterpret_cast<float4*>(&As[d * MT + m4 * 4]) = v;
    }
    // Load enorm into smem once
    for (int i = tid; i < K_ / 4; i += 256) {
        *reinterpret_cast<float4*>(&Es[i * 4]) =
            *reinterpret_cast<const float4*>(&g_enorm[i * 4]);
    }

    auto loadB = [&](int s) {
        int nck = s >> 3, dc = s & 7;
        int k0 = nck * NT, d0 = dc * KC;
        float* dst = Bs + (s & 1) * (KC * NT);
        const float* src = emb + (size_t)d0 * K_ + k0;
#pragma unroll
        for (int i = 0; i < 4; ++i) {
            int t  = i * 256 + tid;
            int kc = t >> 5;
            int n4 = t & 31;
            cp_async16(&dst[kc * NT + n4 * 4], src + (size_t)kc * K_ + n4 * 4);
        }
    };

    float best[8];
    int   bidx[8];
#pragma unroll
    for (int i = 0; i < 8; ++i) { best[i] = FLT_MAX; bidx[i] = 0; }

    float acc[8][8];

    loadB(0);
    asm volatile("cp.async.commit_group;" ::: "memory");
    __syncthreads();   // covers As/Es stores too

    for (int s = 0; s < STAGES; ++s) {
        const int dc = s & 7;
        if (s + 1 < STAGES) {
            loadB(s + 1);
            asm volatile("cp.async.commit_group;" ::: "memory");
            asm volatile("cp.async.wait_group 1;" ::: "memory");
        } else {
            asm volatile("cp.async.wait_group 0;" ::: "memory");
        }
        __syncthreads();

        if (dc == 0) {
#pragma unroll
            for (int i = 0; i < 8; ++i)
#pragma unroll
                for (int j = 0; j < 8; ++j) acc[i][j] = 0.f;
        }

        const float* Bp = Bs + (s & 1) * (KC * NT);
        const float* Ap = As + (dc * KC) * MT;
#pragma unroll 8
        for (int kc = 0; kc < KC; ++kc) {
            float4 a0 = *reinterpret_cast<const float4*>(Ap + kc * MT + ty * 8);
            float4 a1 = *reinterpret_cast<const float4*>(Ap + kc * MT + ty * 8 + 4);
            float4 b0 = *reinterpret_cast<const float4*>(Bp + kc * NT + tx * 8);
            float4 b1 = *reinterpret_cast<const float4*>(Bp + kc * NT + tx * 8 + 4);
            float av[8] = {a0.x, a0.y, a0.z, a0.w, a1.x, a1.y, a1.z, a1.w};
            float bv[8] = {b0.x, b0.y, b0.z, b0.w, b1.x, b1.y, b1.z, b1.w};
#pragma unroll
            for (int i = 0; i < 8; ++i)
#pragma unroll
                for (int j = 0; j < 8; ++j)
                    acc[i][j] = fmaf(av[i], bv[j], acc[i][j]);
        }

        if (dc == 7) {
            // Epilogue: ascending column order -> first-min tie semantics
            const int colbase = (s >> 3) * NT + tx * 8;
#pragma unroll
            for (int j = 0; j < 8; ++j) {
                float en = Es[colbase + j];
#pragma unroll
                for (int i = 0; i < 8; ++i) {
                    float sc = fmaf(-2.f, acc[i][j], en);
                    if (sc < best[i]) { best[i] = sc; bidx[i] = colbase + j; }
                }
            }
        }
        __syncthreads();  // protect buffer reuse by next stage's cp.async
    }

    // Reduce across the 16 threads (tx) sharing each row; lexicographic
    // (value, index) min reproduces jax's first-occurrence argmin.
#pragma unroll
    for (int i = 0; i < 8; ++i) {
        float v = best[i];
        int  ix = bidx[i];
#pragma unroll
        for (int off = 8; off > 0; off >>= 1) {
            float ov = __shfl_xor_sync(0xffffffffu, v, off);
            int   oi = __shfl_xor_sync(0xffffffffu, ix, off);
            if (ov < v || (ov == v && oi < ix)) { v = ov; ix = oi; }
        }
        if (tx == 0) {
            int row = m0 + ty * 8 + i;
            g_idx[row] = ix;
            out_idx_f[row] = (float)ix;   // indices emitted as output dtype
        }
    }
}

// ---------------------------------------------------------------------------
// Kernel 3: gather quantized output + per-block squared-error partial sums.
// out[b][d][h][w] = emb[d][idx[b,h,w]]; coalesced over w; gathers hit L2.
// Deterministic fixed-tree block reduction (no float atomics).
// ---------------------------------------------------------------------------
__global__ __launch_bounds__(256)
void gather_loss_kernel(const float* __restrict__ lat,
                        const float* __restrict__ emb,
                        float* __restrict__ out) {
    int bh = blockIdx.x;              // 0..1023 = (b,h)
    int b  = bh >> 5, h = bh & 31;
    int w  = threadIdx.x & 31;
    int dq = threadIdx.x >> 5;        // 0..7
    int idx = g_idx[bh * 32 + w];
    size_t base = (size_t)b * (D_ * HW) + h * 32 + w;
    float lsum = 0.f;
#pragma unroll 4
    for (int d = dq; d < D_; d += 8) {
        float v = __ldg(&emb[(size_t)d * K_ + idx]);
        float x = lat[base + (size_t)d * HW];
        out[base + (size_t)d * HW] = v;
        float df = v - x;
        lsum = fmaf(df, df, lsum);
    }
    __shared__ float red[256];
    red[threadIdx.x] = lsum;
    __syncthreads();
    for (int st = 128; st > 0; st >>= 1) {
        if (threadIdx.x < st) red[threadIdx.x] += red[threadIdx.x + st];
        __syncthreads();
    }
    if (threadIdx.x == 0) g_part[bh] = red[0];
}

// ---------------------------------------------------------------------------
// Kernel 4: final loss. q_latent_loss == e_latent_loss numerically, so
// loss = (1 + 0.25) * mean((q - x)^2).
// ---------------------------------------------------------------------------
__global__ void loss_kernel(float* __restrict__ out_loss) {
    __shared__ float red[1024];
    int t = threadIdx.x;
    red[t] = g_part[t];
    __syncthreads();
    for (int st = 512; st > 0; st >>= 1) {
        if (t < st) red[t] += red[t + st];
        __syncthreads();
    }
    if (t == 0) out_loss[0] = 1.25f * (red[0] / 8388608.0f);
}

// ---------------------------------------------------------------------------
extern "C" void kernel_launch(void* const* d_in, const int* in_sizes, int n_in,
                              void* d_out, int out_size) {
    const float* lat = (const float*)d_in[0];
    const float* emb = (const float*)d_in[1];
    // Defensive: identify tensors by size (latents 8388608, embeddings 2097152)
    if (n_in >= 2 && in_sizes[0] == D_ * K_) {
        lat = (const float*)d_in[1];
        emb = (const float*)d_in[0];
    }
    float* out = (float*)d_out;

    enorm_kernel<<<K_ / 256, 256>>>(emb);

    cudaFuncSetAttribute(vq_argmin_kernel,
                         cudaFuncAttributeMaxDynamicSharedMemorySize,
                         SMEM_FLOATS * sizeof(float));
    vq_argmin_kernel<<<N_ / MT, 256, SMEM_FLOATS * sizeof(float)>>>(
        lat, emb, out + IDX_OFF);

    gather_loss_kernel<<<B_ * 32, 256>>>(lat, emb, out);
    loss_kernel<<<1, 1024>>>(out + LOSS_OFF);
}

// round 5
// speedup vs baseline: 1.0085x; 1.0085x over previous
#include <cuda_runtime.h>
#include <cstdint>
#include <float.h>

// Problem dims
#define B_  32
#define D_  256
#define K_  8192
#define HW  1024                  // 32*32
#define N_  32768                 // B_*HW
#define OUT_ELEMS 8388608         // B_*D_*HW
#define LOSS_OFF  OUT_ELEMS
#define IDX_OFF   (OUT_ELEMS + 1)

// GEMM tiling
#define MT 128
#define NT 128
#define KC 32
#define NCHUNKS (K_ / NT)         // 64
#define DCHUNKS (D_ / KC)         // 8
#define STAGES  (NCHUNKS * DCHUNKS)  // 512
#define SMEM_FLOATS (D_*MT + 2*KC*NT + K_)   // 32768 + 8192 + 8192 = 49152 floats = 192KB

// Scratch (no allocations allowed)
__device__ __align__(16) float g_enorm[K_];
__device__ __align__(16) int   g_idx[N_];
__device__ __align__(16) float g_part[1024];

// ---------------------------------------------------------------------------
// Kernel 1: enorm[k] = sum_d e[d,k]^2
// ---------------------------------------------------------------------------
__global__ void enorm_kernel(const float* __restrict__ emb) {
    int k = blockIdx.x * blockDim.x + threadIdx.x;
    float s = 0.f;
#pragma unroll 8
    for (int d = 0; d < D_; ++d) {
        float v = emb[(size_t)d * K_ + k];
        s = fmaf(v, v, s);
    }
    g_enorm[k] = s;
}

// ---------------------------------------------------------------------------
// Kernel 2: fused fp32 GEMM + row argmin.
//   score(n,k) = enorm[k] - 2 * dot(z_n, e_k)   (||z||^2 dropped: row-const)
// A tile [256][128] fully resident in smem; B streamed 32x128 double-buffered
// via cp.async; per-128-col epilogue updates running (min, argmin) in regs.
// ---------------------------------------------------------------------------
__device__ __forceinline__ void cp_async16(void* dst, const void* src) {
    uint32_t s = (uint32_t)__cvta_generic_to_shared(dst);
    asm volatile("cp.async.cg.shared.global [%0], [%1], 16;" :: "r"(s), "l"(src));
}

__global__ __launch_bounds__(256, 1)
void vq_argmin_kernel(const float* __restrict__ lat,
                      const float* __restrict__ emb,
                      float* __restrict__ out_idx_f) {
    extern __shared__ float smem[];
    float* As = smem;                 // [256][128]  (d-major, m contiguous)
    float* Bs = As + D_ * MT;         // [2][32][128]
    float* Es = Bs + 2 * KC * NT;     // [8192]

    const int tid = threadIdx.x;
    const int tx  = tid & 15;         // 16 col-groups of 8
    const int ty  = tid >> 4;         // 16 row-groups of 8
    const int m0  = blockIdx.x * MT;  // 128-row tile, always within one batch b
    const int b   = m0 >> 10;
    const int hw0 = m0 & (HW - 1);

    const float* Abase = lat + (size_t)b * (D_ * HW) + hw0;

    // Load full A tile: As[d][m] = latents[b][d][hw0+m]  (coalesced over m)
    for (int i = tid; i < D_ * (MT / 4); i += 256) {
        int d  = i >> 5;              // 32 float4 per d-row
        int m4 = i & 31;
        float4 v = *reinterpret_cast<const float4*>(Abase + (size_t)d * HW + m4 * 4);
        *reinterpret_cast<float4*>(&As[d * MT + m4 * 4]) = v;
    }
    // Load enorm into smem once
    for (int i = tid; i < K_ / 4; i += 256) {
        *reinterpret_cast<float4*>(&Es[i * 4]) =
            *reinterpret_cast<const float4*>(&g_enorm[i * 4]);
    }

    auto loadB = [&](int s) {
        int nck = s >> 3, dc = s & 7;
        int k0 = nck * NT, d0 = dc * KC;
        float* dst = Bs + (s & 1) * (KC * NT);
        const float* src = emb + (size_t)d0 * K_ + k0;
#pragma unroll
        for (int i = 0; i < 4; ++i) {
            int t  = i * 256 + tid;
            int kc = t >> 5;
            int n4 = t & 31;
            cp_async16(&dst[kc * NT + n4 * 4], src + (size_t)kc * K_ + n4 * 4);
        }
    };

    float best[8];
    int   bidx[8];
#pragma unroll
    for (int i = 0; i < 8; ++i) { best[i] = FLT_MAX; bidx[i] = 0; }

    float acc[8][8];

    loadB(0);
    asm volatile("cp.async.commit_group;" ::: "memory");
    __syncthreads();   // covers As/Es stores too

    for (int s = 0; s < STAGES; ++s) {
        const int dc = s & 7;
        if (s + 1 < STAGES) {
            loadB(s + 1);
            asm volatile("cp.async.commit_group;" ::: "memory");
            asm volatile("cp.async.wait_group 1;" ::: "memory");
        } else {
            asm volatile("cp.async.wait_group 0;" ::: "memory");
        }
        __syncthreads();

        if (dc == 0) {
#pragma unroll
            for (int i = 0; i < 8; ++i)
#pragma unroll
                for (int j = 0; j < 8; ++j) acc[i][j] = 0.f;
        }

        const float* Bp = Bs + (s & 1) * (KC * NT);
        const float* Ap = As + (dc * KC) * MT;
#pragma unroll 8
        for (int kc = 0; kc < KC; ++kc) {
            float4 a0 = *reinterpret_cast<const float4*>(Ap + kc * MT + ty * 8);
            float4 a1 = *reinterpret_cast<const float4*>(Ap + kc * MT + ty * 8 + 4);
            float4 b0 = *reinterpret_cast<const float4*>(Bp + kc * NT + tx * 8);
            float4 b1 = *reinterpret_cast<const float4*>(Bp + kc * NT + tx * 8 + 4);
            float av[8] = {a0.x, a0.y, a0.z, a0.w, a1.x, a1.y, a1.z, a1.w};
            float bv[8] = {b0.x, b0.y, b0.z, b0.w, b1.x, b1.y, b1.z, b1.w};
#pragma unroll
            for (int i = 0; i < 8; ++i)
#pragma unroll
                for (int j = 0; j < 8; ++j)
                    acc[i][j] = fmaf(av[i], bv[j], acc[i][j]);
        }

        if (dc == 7) {
            // Epilogue: ascending column order -> first-min tie semantics
            const int colbase = (s >> 3) * NT + tx * 8;
#pragma unroll
            for (int j = 0; j < 8; ++j) {
                float en = Es[colbase + j];
#pragma unroll
                for (int i = 0; i < 8; ++i) {
                    float sc = fmaf(-2.f, acc[i][j], en);
                    if (sc < best[i]) { best[i] = sc; bidx[i] = colbase + j; }
                }
            }
        }
        __syncthreads();  // protect buffer reuse by next stage's cp.async
    }

    // Reduce across the 16 threads (tx) sharing each row; lexicographic
    // (value, index) min reproduces jax's first-occurrence argmin.
#pragma unroll
    for (int i = 0; i < 8; ++i) {
        float v = best[i];
        int  ix = bidx[i];
#pragma unroll
        for (int off = 8; off > 0; off >>= 1) {
            float ov = __shfl_xor_sync(0xffffffffu, v, off);
            int   oi = __shfl_xor_sync(0xffffffffu, ix, off);
            if (ov < v || (ov == v && oi < ix)) { v = ov; ix = oi; }
        }
        if (tx == 0) {
            int row = m0 + ty * 8 + i;
            g_idx[row] = ix;
            out_idx_f[row] = (float)ix;   // indices emitted as output dtype
        }
    }
}

// ---------------------------------------------------------------------------
// Kernel 3: gather quantized output + per-block squared-error partial sums.
// out[b][d][h][w] = emb[d][idx[b,h,w]]; coalesced over w; gathers hit L2.
// Deterministic fixed-tree block reduction (no float atomics).
// ---------------------------------------------------------------------------
__global__ __launch_bounds__(256)
void gather_loss_kernel(const float* __restrict__ lat,
                        const float* __restrict__ emb,
                        float* __restrict__ out) {
    int bh = blockIdx.x;              // 0..1023 = (b,h)
    int b  = bh >> 5, h = bh & 31;
    int w  = threadIdx.x & 31;
    int dq = threadIdx.x >> 5;        // 0..7
    int idx = g_idx[bh * 32 + w];
    size_t base = (size_t)b * (D_ * HW) + h * 32 + w;
    float lsum = 0.f;
#pragma unroll 4
    for (int d = dq; d < D_; d += 8) {
        float v = __ldg(&emb[(size_t)d * K_ + idx]);
        float x = lat[base + (size_t)d * HW];
        out[base + (size_t)d * HW] = v;
        float df = v - x;
        lsum = fmaf(df, df, lsum);
    }
    __shared__ float red[256];
    red[threadIdx.x] = lsum;
    __syncthreads();
    for (int st = 128; st > 0; st >>= 1) {
        if (threadIdx.x < st) red[threadIdx.x] += red[threadIdx.x + st];
        __syncthreads();
    }
    if (threadIdx.x == 0) g_part[bh] = red[0];
}

// ---------------------------------------------------------------------------
// Kernel 4: final loss. q_latent_loss == e_latent_loss numerically, so
// loss = (1 + 0.25) * mean((q - x)^2).
// ---------------------------------------------------------------------------
__global__ void loss_kernel(float* __restrict__ out_loss) {
    __shared__ float red[1024];
    int t = threadIdx.x;
    red[t] = g_part[t];
    __syncthreads();
    for (int st = 512; st > 0; st >>= 1) {
        if (t < st) red[t] += red[t + st];
        __syncthreads();
    }
    if (t == 0) out_loss[0] = 1.25f * (red[0] / 8388608.0f);
}

// ---------------------------------------------------------------------------
extern "C" void kernel_launch(void* const* d_in, const int* in_sizes, int n_in,
                              void* d_out, int out_size) {
    const float* lat = (const float*)d_in[0];
    const float* emb = (const float*)d_in[1];
    // Defensive: identify tensors by size (latents 8388608, embeddings 2097152)
    if (n_in >= 2 && in_sizes[0] == D_ * K_) {
        lat = (const float*)d_in[1];
        emb = (const float*)d_in[0];
    }
    float* out = (float*)d_out;

    enorm_kernel<<<K_ / 256, 256>>>(emb);

    cudaFuncSetAttribute(vq_argmin_kernel,
                         cudaFuncAttributeMaxDynamicSharedMemorySize,
                         SMEM_FLOATS * sizeof(float));
    vq_argmin_kernel<<<N_ / MT, 256, SMEM_FLOATS * sizeof(float)>>>(
        lat, emb, out + IDX_OFF);

    gather_loss_kernel<<<B_ * 32, 256>>>(lat, emb, out);
    loss_kernel<<<1, 1024>>>(out + LOSS_OFF);
}

// round 7
// speedup vs baseline: 5.1654x; 5.1218x over previous
#include <cuda_runtime.h>
#include <cuda_bf16.h>
#include <cstdint>
#include <float.h>

// ---------------------------------------------------------------- problem dims
#define B_  32
#define D_  256
#define K_  8192
#define HW  1024
#define N_  32768
#define OUT_ELEMS 8388608
#define LOSS_OFF  OUT_ELEMS
#define IDX_OFF   (OUT_ELEMS + 1)

// ---------------------------------------------------------------- GEMM tiling
#define NCHUNK 64                    // 64 chunks of 128 codes
#define AS_STRIDE 264                // bf16 elems per A smem row (256 + 8 pad)
#define BS_STRIDE 136                // bf16 elems per B smem row (128 + 8 pad)
#define SM_A 0
#define SM_B (128 * AS_STRIDE * 2)   // 67584
#define BUFB (256 * BS_STRIDE * 2)   // 69632
#define SM_TOTAL (SM_B + 2 * BUFB)   // 206848

// ---------------------------------------------------------------- scratch
__device__ __align__(16) float g_enorm[K_];
__device__ __align__(16) int   g_idx[N_];
__device__ __align__(16) float g_part[1024];
__device__ __align__(16) int   g_top4[N_ * 4];
__device__ __align__(16) __nv_bfloat16 g_latT[(size_t)N_ * D_];   // [n][d] row-major
__device__ __align__(16) __nv_bfloat16 g_embBf[(size_t)D_ * K_];  // [d][k] row-major
__device__ __align__(16) float g_embT[(size_t)K_ * D_];           // [k][d] fp32

// ---------------------------------------------------------------- helpers
__device__ __forceinline__ uint32_t smem_u32(const void* p) {
    return (uint32_t)__cvta_generic_to_shared(p);
}
__device__ __forceinline__ void cp_async16(uint32_t dst, const void* src) {
    asm volatile("cp.async.cg.shared.global [%0], [%1], 16;" :: "r"(dst), "l"(src));
}
__device__ __forceinline__ void ldsm_x4(uint32_t* r, uint32_t addr) {
    asm volatile("ldmatrix.sync.aligned.m8n8.x4.shared.b16 {%0,%1,%2,%3}, [%4];"
                 : "=r"(r[0]), "=r"(r[1]), "=r"(r[2]), "=r"(r[3]) : "r"(addr));
}
__device__ __forceinline__ void ldsm_x4_t(uint32_t* r, uint32_t addr) {
    asm volatile("ldmatrix.sync.aligned.m8n8.x4.trans.shared.b16 {%0,%1,%2,%3}, [%4];"
                 : "=r"(r[0]), "=r"(r[1]), "=r"(r[2]), "=r"(r[3]) : "r"(addr));
}
__device__ __forceinline__ void mma_bf16(float* c, const uint32_t* a, uint32_t b0, uint32_t b1) {
    asm volatile(
        "mma.sync.aligned.m16n8k16.row.col.f32.bf16.bf16.f32 "
        "{%0,%1,%2,%3}, {%4,%5,%6,%7}, {%8,%9}, {%0,%1,%2,%3};"
        : "+f"(c[0]), "+f"(c[1]), "+f"(c[2]), "+f"(c[3])
        : "r"(a[0]), "r"(a[1]), "r"(a[2]), "r"(a[3]), "r"(b0), "r"(b1));
}

// ---------------------------------------------------------------- kernel 1: enorm
__global__ void enorm_kernel(const float* __restrict__ emb) {
    int k = blockIdx.x * blockDim.x + threadIdx.x;
    float s = 0.f;
#pragma unroll 8
    for (int d = 0; d < D_; ++d) {
        float v = emb[(size_t)d * K_ + k];
        s = fmaf(v, v, s);
    }
    g_enorm[k] = s;
}

// ---------------------------------------------------------------- kernel 2: latents -> bf16 [n][d]
__global__ void latconv_kernel(const float* __restrict__ lat) {
    __shared__ float t[32][33];
    int b = blockIdx.z, hw0 = blockIdx.x * 32, d0 = blockIdx.y * 32;
    t[threadIdx.y][threadIdx.x] =
        lat[((size_t)b * D_ + d0 + threadIdx.y) * HW + hw0 + threadIdx.x];
    __syncthreads();
    g_latT[((size_t)(b * HW + hw0 + threadIdx.y)) * D_ + d0 + threadIdx.x] =
        __float2bfloat16(t[threadIdx.x][threadIdx.y]);
}

// ---------------------------------------------------------------- kernel 3: embeddings -> bf16 [d][k]
__global__ void embconv_kernel(const float* __restrict__ emb) {
    size_t i = (size_t)blockIdx.x * blockDim.x + threadIdx.x;   // over D_*K_/4
    float4 v = reinterpret_cast<const float4*>(emb)[i];
    __nv_bfloat162 lo = __floats2bfloat162_rn(v.x, v.y);
    __nv_bfloat162 hi = __floats2bfloat162_rn(v.z, v.w);
    uint2 pk;
    pk.x = *reinterpret_cast<uint32_t*>(&lo);
    pk.y = *reinterpret_cast<uint32_t*>(&hi);
    reinterpret_cast<uint2*>(g_embBf)[i] = pk;
}

// ---------------------------------------------------------------- kernel 4: embeddings -> fp32 [k][d] for rescore
__global__ void embT_kernel(const float* __restrict__ emb) {
    __shared__ float t[32][33];
    int kb = blockIdx.x * 32, db = blockIdx.y * 32;
    t[threadIdx.y][threadIdx.x] = emb[(size_t)(db + threadIdx.y) * K_ + kb + threadIdx.x];
    __syncthreads();
    g_embT[(size_t)(kb + threadIdx.y) * D_ + db + threadIdx.x] = t[threadIdx.x][threadIdx.y];
}

// ---------------------------------------------------------------- kernel 5: bf16 mma.sync GEMM + per-row candidates
__global__ __launch_bounds__(256, 1)
void vq_mma_kernel() {
    extern __shared__ char smem[];
    const uint32_t sb = smem_u32(smem);
    const int tid = threadIdx.x, lane = tid & 31, wid = tid >> 5;
    const int wm = wid & 1;        // 0-1: 64-row half
    const int wn = wid >> 1;       // 0-3: 32-col quarter

    // preload A tile (128 x 256 bf16, padded rows) + B chunk 0, one group
    {
        const char* at = (const char*)(g_latT + (size_t)blockIdx.x * 128 * D_);
        for (int i = tid; i < 4096; i += 256) {
            int r = i >> 5, s = i & 31;
            cp_async16(sb + SM_A + r * (AS_STRIDE * 2) + s * 16, at + r * 512 + s * 16);
        }
        const char* bt = (const char*)g_embBf;
        for (int i = tid; i < 4096; i += 256) {
            int r = i >> 4, s = i & 15;
            cp_async16(sb + SM_B + r * (BS_STRIDE * 2) + s * 16,
                       bt + (size_t)r * (K_ * 2) + s * 16);
        }
        asm volatile("cp.async.commit_group;" ::: "memory");
    }

    // per-lane ldmatrix base addresses
    uint32_t a_addr[4];
#pragma unroll
    for (int mf = 0; mf < 4; ++mf)
        a_addr[mf] = sb + SM_A + (wm * 64 + mf * 16 + (lane & 15)) * (AS_STRIDE * 2)
                   + (lane >> 4) * 16;
    const uint32_t b_off = (((lane >> 3) & 1) * 8 + (lane & 7)) * (BS_STRIDE * 2)
                         + (wn * 32 + (lane >> 4) * 8) * 2;

    // per-(thread,row) top-2 over this thread's disjoint 512-col subset
    float sv[8][2];
    int   si[8][2];
#pragma unroll
    for (int r = 0; r < 8; ++r) { sv[r][0] = sv[r][1] = FLT_MAX; si[r][0] = si[r][1] = 0; }

    for (int u = 0; u < NCHUNK; ++u) {
        if (u + 1 < NCHUNK) {
            const char* bt = (const char*)g_embBf + (size_t)(u + 1) * 256;
            uint32_t bd = sb + SM_B + ((u + 1) & 1) * BUFB;
            for (int i = tid; i < 4096; i += 256) {
                int r = i >> 4, s = i & 15;
                cp_async16(bd + r * (BS_STRIDE * 2) + s * 16,
                           bt + (size_t)r * (K_ * 2) + s * 16);
            }
            asm volatile("cp.async.commit_group;" ::: "memory");
            asm volatile("cp.async.wait_group 1;" ::: "memory");
        } else {
            asm volatile("cp.async.wait_group 0;" ::: "memory");
        }
        __syncthreads();

        float acc[4][4][4];
#pragma unroll
        for (int mf = 0; mf < 4; ++mf)
#pragma unroll
            for (int nf = 0; nf < 4; ++nf)
#pragma unroll
                for (int q = 0; q < 4; ++q) acc[mf][nf][q] = 0.f;

        const uint32_t bbase = sb + SM_B + (u & 1) * BUFB + b_off;
#pragma unroll 4
        for (int ks = 0; ks < 16; ++ks) {
            uint32_t ar[4][4];
#pragma unroll
            for (int mf = 0; mf < 4; ++mf) ldsm_x4(ar[mf], a_addr[mf] + ks * 32);
            uint32_t br[2][4];
#pragma unroll
            for (int p = 0; p < 2; ++p)
                ldsm_x4_t(br[p], bbase + ks * 16 * (BS_STRIDE * 2) + p * 32);
#pragma unroll
            for (int mf = 0; mf < 4; ++mf)
#pragma unroll
                for (int nf = 0; nf < 4; ++nf)
                    mma_bf16(acc[mf][nf], ar[mf],
                             br[nf >> 1][(nf & 1) * 2], br[nf >> 1][(nf & 1) * 2 + 1]);
        }

        // epilogue: sc = enorm[c] - 2*dot; track top-2 per row subset.
        const int cb0 = (u << 7) + wn * 32 + (lane & 3) * 2;
#pragma unroll
        for (int nf = 0; nf < 4; ++nf) {
            const int c0 = cb0 + nf * 8;
            float2 e = __ldg(reinterpret_cast<const float2*>(&g_enorm[c0]));
#pragma unroll
            for (int mf = 0; mf < 4; ++mf) {
#pragma unroll
                for (int half = 0; half < 2; ++half) {
                    const int rs = mf * 2 + half;
                    float v0 = fmaf(-2.f, acc[mf][nf][half * 2 + 0], e.x);
                    float v1 = fmaf(-2.f, acc[mf][nf][half * 2 + 1], e.y);
                    if (v0 < sv[rs][1]) {
                        if (v0 < sv[rs][0]) { sv[rs][1] = sv[rs][0]; si[rs][1] = si[rs][0];
                                              sv[rs][0] = v0; si[rs][0] = c0; }
                        else                { sv[rs][1] = v0; si[rs][1] = c0; }
                    }
                    if (v1 < sv[rs][1]) {
                        if (v1 < sv[rs][0]) { sv[rs][1] = sv[rs][0]; si[rs][1] = si[rs][0];
                                              sv[rs][0] = v1; si[rs][0] = c0 + 1; }
                        else                { sv[rs][1] = v1; si[rs][1] = c0 + 1; }
                    }
                }
            }
        }
        __syncthreads();   // protect B buffer reuse by next prefetch
    }

    // merge: 16 subsets x top-2 = 32 candidates per row -> top-4
    struct Pair { float v; int i; };
    Pair* pr = reinterpret_cast<Pair*>(smem);   // [128][32], 32KB (A region, done)
    __syncthreads();
#pragma unroll
    for (int rs = 0; rs < 8; ++rs) {
        int r = wm * 64 + (rs >> 1) * 16 + (lane >> 2) + (rs & 1) * 8;
        int sub = wn * 4 + (lane & 3);
        pr[r * 32 + sub * 2 + 0] = { sv[rs][0], si[rs][0] };
        pr[r * 32 + sub * 2 + 1] = { sv[rs][1], si[rs][1] };
    }
    __syncthreads();
    if (tid < 128) {
        float bv[4] = {FLT_MAX, FLT_MAX, FLT_MAX, FLT_MAX};
        int   bi[4] = {0x7fffffff, 0x7fffffff, 0x7fffffff, 0x7fffffff};
        for (int j = 0; j < 32; ++j) {
            float v = pr[tid * 32 + j].v;
            int   i = pr[tid * 32 + j].i;
            if (v < bv[3] || (v == bv[3] && i < bi[3])) {
#pragma unroll
                for (int s = 3; s >= 0; --s) {
                    bool ins = (s == 0) ||
                               (pr ? (bv[s-1] < v || (bv[s-1] == v && bi[s-1] < i)) : false);
                    if (s < 3) { /* shifted below */ }
                    (void)ins;
                }
                // simple sorted insert (4-deep)
                if (v < bv[0] || (v == bv[0] && i < bi[0])) {
                    bv[3]=bv[2]; bi[3]=bi[2]; bv[2]=bv[1]; bi[2]=bi[1];
                    bv[1]=bv[0]; bi[1]=bi[0]; bv[0]=v; bi[0]=i;
                } else if (v < bv[1] || (v == bv[1] && i < bi[1])) {
                    bv[3]=bv[2]; bi[3]=bi[2]; bv[2]=bv[1]; bi[2]=bi[1];
                    bv[1]=v; bi[1]=i;
                } else if (v < bv[2] || (v == bv[2] && i < bi[2])) {
                    bv[3]=bv[2]; bi[3]=bi[2]; bv[2]=v; bi[2]=i;
                } else {
                    bv[3]=v; bi[3]=i;
                }
            }
        }
        int row = blockIdx.x * 128 + tid;
#pragma unroll
        for (int s = 0; s < 4; ++s) g_top4[row * 4 + s] = bi[s];
    }
}

// ---------------------------------------------------------------- kernel 6: exact fp32 rescore of top-4
__global__ __launch_bounds__(256)
void rescore_kernel(const float* __restrict__ lat, float* __restrict__ out_idx_f) {
    int row = blockIdx.x * 32 + (threadIdx.x >> 3);
    int l8  = threadIdx.x & 7;
    int b = row >> 10, hw = row & (HW - 1);
    const float* z = lat + (size_t)b * (D_ * HW) + hw;
    int cand[4];
#pragma unroll
    for (int c = 0; c < 4; ++c) cand[c] = g_top4[row * 4 + c];
    float dot[4] = {0.f, 0.f, 0.f, 0.f};
    for (int d = l8; d < D_; d += 8) {
        float zv = z[(size_t)d * HW];
#pragma unroll
        for (int c = 0; c < 4; ++c)
            dot[c] = fmaf(zv, g_embT[(size_t)cand[c] * D_ + d], dot[c]);
    }
#pragma unroll
    for (int c = 0; c < 4; ++c) {
#pragma unroll
        for (int off = 4; off > 0; off >>= 1)
            dot[c] += __shfl_down_sync(0xffffffffu, dot[c], off, 8);
    }
    if (l8 == 0) {
        float bv = FLT_MAX; int bi = 0x7fffffff;
#pragma unroll
        for (int c = 0; c < 4; ++c) {
            float dist = fmaf(-2.f, dot[c], g_enorm[cand[c]]);
            if (dist < bv || (dist == bv && cand[c] < bi)) { bv = dist; bi = cand[c]; }
        }
        g_idx[row] = bi;
        out_idx_f[row] = (float)bi;
    }
}

// ---------------------------------------------------------------- kernel 7: gather + loss partials
__global__ __launch_bounds__(256)
void gather_loss_kernel(const float* __restrict__ lat,
                        const float* __restrict__ emb,
                        float* __restrict__ out) {
    int bh = blockIdx.x;
    int b = bh >> 5, h = bh & 31;
    int w = threadIdx.x & 31;
    int dq = threadIdx.x >> 5;
    int idx = g_idx[bh * 32 + w];
    size_t base = (size_t)b * (D_ * HW) + h * 32 + w;
    float lsum = 0.f;
#pragma unroll 4
    for (int d = dq; d < D_; d += 8) {
        float v = __ldg(&emb[(size_t)d * K_ + idx]);
        float x = lat[base + (size_t)d * HW];
        out[base + (size_t)d * HW] = v;
        float df = v - x;
        lsum = fmaf(df, df, lsum);
    }
    __shared__ float red[256];
    red[threadIdx.x] = lsum;
    __syncthreads();
    for (int st = 128; st > 0; st >>= 1) {
        if (threadIdx.x < st) red[threadIdx.x] += red[threadIdx.x + st];
        __syncthreads();
    }
    if (threadIdx.x == 0) g_part[bh] = red[0];
}

// ---------------------------------------------------------------- kernel 8: final loss
__global__ void loss_kernel(float* __restrict__ out_loss) {
    __shared__ float red[1024];
    int t = threadIdx.x;
    red[t] = g_part[t];
    __syncthreads();
    for (int st = 512; st > 0; st >>= 1) {
        if (t < st) red[t] += red[t + st];
        __syncthreads();
    }
    if (t == 0) out_loss[0] = 1.25f * (red[0] / 8388608.0f);
}

// ----------------------------------------------------------------
extern "C" void kernel_launch(void* const* d_in, const int* in_sizes, int n_in,
                              void* d_out, int out_size) {
    const float* lat = (const float*)d_in[0];
    const float* emb = (const float*)d_in[1];
    if (n_in >= 2 && in_sizes[0] == D_ * K_) {   // defensive size-based ident
        lat = (const float*)d_in[1];
        emb = (const float*)d_in[0];
    }
    float* out = (float*)d_out;

    enorm_kernel<<<K_ / 256, 256>>>(emb);
    latconv_kernel<<<dim3(HW / 32, D_ / 32, B_), dim3(32, 32)>>>(lat);
    embconv_kernel<<<(D_ * K_ / 4) / 256, 256>>>(emb);
    embT_kernel<<<dim3(K_ / 32, D_ / 32), dim3(32, 32)>>>(emb);

    cudaFuncSetAttribute(vq_mma_kernel,
                         cudaFuncAttributeMaxDynamicSharedMemorySize, SM_TOTAL);
    vq_mma_kernel<<<N_ / 128, 256, SM_TOTAL>>>();

    rescore_kernel<<<N_ / 32, 256>>>(lat, out + IDX_OFF);
    gather_loss_kernel<<<B_ * 32, 256>>>(lat, emb, out);
    loss_kernel<<<1, 1024>>>(out + LOSS_OFF);
}